// round 4
// baseline (speedup 1.0000x reference)
#include <cuda_runtime.h>
#include <cuda_bf16.h>

// Problem shapes (fixed by the dataset)
#define BB   16384
#define CC   10
#define KK   8
#define DIM  128

#define WARPS_PER_BLOCK 8
#define NBLK (BB / WARPS_PER_BLOCK)   // 2048

// Scratch (device globals: allocation-guard-safe)
__device__ float g_part[NBLK];

// Stage 1: one WARP per example, lane l owns dims [4l..4l+3] as float4.
// All 18 gather loads issued into distinct live registers => MLP = 18
// (register-limited MLP was the R3 bottleneck: regs=32 forced MLP~5).
__global__ void __launch_bounds__(32 * WARPS_PER_BLOCK, 1) cbow_main(
    const int*   __restrict__ contexts,   // [B, C]
    const int*   __restrict__ focus,      // [B, K]
    const float* __restrict__ wmask,      // [B, K]
    const float* __restrict__ labels,     // [B, K]
    const float* __restrict__ ctx_emb,    // [VOCAB, DIM]
    const float* __restrict__ neg_emb)    // [VOCAB, DIM]
{
    const int lane = threadIdx.x & 31;
    const int wid  = threadIdx.x >> 5;
    const int b    = blockIdx.x * WARPS_PER_BLOCK + wid;

    __shared__ float s_row[WARPS_PER_BLOCK];

    // Per-lane index/label staging (lanes < C / < K own one entry each)
    int   ctx_i = (lane < CC) ? contexts[b * CC + lane] : 0;
    int   foc_i = (lane < KK) ? focus[b * KK + lane]    : 0;
    float w     = (lane < KK) ? wmask [b * KK + lane]   : 0.0f;
    float y     = (lane < KK) ? labels[b * KK + lane]   : 0.0f;

    // ---- Issue ALL 18 row loads first, into distinct registers ----
    float4 cv[CC];
#pragma unroll
    for (int c = 0; c < CC; ++c) {
        int row = __shfl_sync(0xffffffffu, ctx_i, c);
        cv[c] = __ldg((const float4*)&ctx_emb[(size_t)row * DIM + lane * 4]);
    }
    float4 tv[KK];
#pragma unroll
    for (int k = 0; k < KK; ++k) {
        int row = __shfl_sync(0xffffffffu, foc_i, k);
        tv[k] = __ldg((const float4*)&neg_emb[(size_t)row * DIM + lane * 4]);
    }

    // ---- Sum-pool context embedding (tree over 10 float4s) ----
    float4 src = cv[0];
#pragma unroll
    for (int c = 1; c < CC; ++c) {
        src.x += cv[c].x; src.y += cv[c].y; src.z += cv[c].z; src.w += cv[c].w;
    }

    // ---- K dot products; butterfly reduce (8 independent shuffle chains) ----
    float pred_mine = 0.0f;
#pragma unroll
    for (int k = 0; k < KK; ++k) {
        float d = src.x * tv[k].x + src.y * tv[k].y
                + src.z * tv[k].z + src.w * tv[k].w;
        d += __shfl_xor_sync(0xffffffffu, d, 16);
        d += __shfl_xor_sync(0xffffffffu, d, 8);
        d += __shfl_xor_sync(0xffffffffu, d, 4);
        d += __shfl_xor_sync(0xffffffffu, d, 2);
        d += __shfl_xor_sync(0xffffffffu, d, 1);
        if (lane == k) pred_mine = d;
    }

    // Lane k (< K) computes its weighted BCE term once
    float bce = 0.0f;
    if (lane < KK) {
        // logaddexp(0, x) = max(x,0) + log1p(exp(-|x|))  (stable softplus)
        float sp = fmaxf(pred_mine, 0.0f) + log1pf(expf(-fabsf(pred_mine)));
        bce = w * (sp - pred_mine * y);
    }

    // num = sum_k bce, den = sum_k w  (w is 0 on lanes >= K)
    float num = bce, den = w;
#pragma unroll
    for (int o = 16; o > 0; o >>= 1) {
        num += __shfl_xor_sync(0xffffffffu, num, o);
        den += __shfl_xor_sync(0xffffffffu, den, o);
    }

    // Per-warp row loss -> block partial sum (fused, saves one reduce kernel)
    if (lane == 0) s_row[wid] = num / den;
    __syncthreads();
    if (threadIdx.x == 0) {
        float acc = 0.0f;
#pragma unroll
        for (int i = 0; i < WARPS_PER_BLOCK; ++i) acc += s_row[i];
        g_part[blockIdx.x] = acc;
    }
}

// Stage 2: single block reduces 2048 block partials -> scalar mean
__global__ void __launch_bounds__(1024) cbow_reduce(float* __restrict__ out)
{
    __shared__ double s_acc[32];
    const int tid  = threadIdx.x;
    const int lane = tid & 31;
    const int warp = tid >> 5;

    double v = (double)g_part[tid] + (double)g_part[tid + 1024];
#pragma unroll
    for (int o = 16; o > 0; o >>= 1)
        v += __shfl_xor_sync(0xffffffffu, v, o);
    if (lane == 0) s_acc[warp] = v;
    __syncthreads();

    if (tid < 32) {
        double t = s_acc[tid];
#pragma unroll
        for (int o = 16; o > 0; o >>= 1)
            t += __shfl_xor_sync(0xffffffffu, t, o);
        if (tid == 0) out[0] = (float)(t / (double)BB);
    }
}

extern "C" void kernel_launch(void* const* d_in, const int* in_sizes, int n_in,
                              void* d_out, int out_size)
{
    const int*   contexts = (const int*)  d_in[0];   // [B, C] int32
    const int*   focus    = (const int*)  d_in[1];   // [B, K] int32
    const float* wmask    = (const float*)d_in[2];   // [B, K] f32
    const float* labels   = (const float*)d_in[3];   // [B, K] f32
    const float* ctx_emb  = (const float*)d_in[4];   // [VOCAB, DIM] f32
    const float* neg_emb  = (const float*)d_in[5];   // [VOCAB, DIM] f32
    float* out = (float*)d_out;

    cbow_main<<<NBLK, 32 * WARPS_PER_BLOCK>>>(
        contexts, focus, wmask, labels, ctx_emb, neg_emb);
    cbow_reduce<<<1, 1024>>>(out);
}